// round 3
// baseline (speedup 1.0000x reference)
#include <cuda_runtime.h>
#include <cuda_bf16.h>
#include <math.h>

#define BB   16
#define CIN  3
#define SS   16384
#define HID  64
#define NM   16
#define NL   4
#define NPSP 500
#define NPFR 200
#define ED   8

// ---------------- scratch (__device__ globals; no allocation) ----------------
__device__ float d_hA[BB * HID * SS];            // 64 MB
__device__ float d_hB[BB * HID * SS];            // 64 MB
__device__ float d_twc[SS * NM];                 // cos(2pi k s / S)
__device__ float d_tws[SS * NM];                 // sin(2pi k s / S)
__device__ float d_part[BB * 64 * HID * 32];     // split-K partials, 8 MB
__device__ float d_Xf[BB * HID * 32];            // cols 0..15: sum x*cos (=Re), 16..31: sum x*sin (=-Im)
__device__ float d_Cf[BB * HID * 32];            // combined scaled spectrum: 0..15 Re', 16..31 Im'
__device__ int   d_idx[BB * SS];                 // spatial hash index
__device__ int   d_cnt[BB * NPSP];               // per-batch histogram
__device__ float d_P[NPSP * HID];                // projected spatial patterns
__device__ float d_gw[BB];                       // gate weight w1 per batch

__device__ __forceinline__ const float* hbuf_c(int s) { return s ? d_hB : d_hA; }
__device__ __forceinline__ float*       hbuf(int s)   { return s ? d_hB : d_hA; }

// ---------------- twiddles ----------------
__global__ void k_init_tw() {
    int i = blockIdx.x * 256 + threadIdx.x;        // i < SS*NM
    int s = i / NM, k = i % NM;
    long m = ((long)s * (long)k) % SS;
    double th = 6.283185307179586476925286766559 * (double)m / (double)SS;
    d_twc[i] = (float)cos(th);
    d_tws[i] = (float)sin(th);
}

// ---------------- lift: h = x @ lift_W + lift_b ----------------
__global__ void k_lift(const float* __restrict__ x, const float* __restrict__ W,
                       const float* __restrict__ bias) {
    int i = blockIdx.x * 256 + threadIdx.x;        // over B*S
    int b = i >> 14;
    int s = i & (SS - 1);
    float x0 = x[(b * CIN + 0) * SS + s];
    float x1 = x[(b * CIN + 1) * SS + s];
    float x2 = x[(b * CIN + 2) * SS + s];
#pragma unroll
    for (int c = 0; c < HID; c++) {
        float v = fmaf(x0, __ldg(&W[0 * HID + c]),
                  fmaf(x1, __ldg(&W[1 * HID + c]),
                  fmaf(x2, __ldg(&W[2 * HID + c]), __ldg(&bias[c]))));
        d_hA[(b * HID + c) * SS + s] = v;
    }
}

// ---------------- per-layer: precompute P rows + zero histogram ----------------
__global__ void k_prep(const float* __restrict__ sp_emb, const float* __restrict__ sp_W,
                       const float* __restrict__ sp_b, int layer) {
    int i = blockIdx.x * 256 + threadIdx.x;        // 125 blocks * 256 = 32000
    if (i < NPSP * HID) {
        int p = i / HID, c = i % HID;
        const float* e = sp_emb + (layer * NPSP + p) * ED;
        const float* W = sp_W + layer * ED * HID;
        float acc = sp_b[layer * HID + c];
#pragma unroll
        for (int j = 0; j < ED; j++) acc = fmaf(e[j], W[j * HID + c], acc);
        d_P[i] = acc;
    }
    if (i < BB * NPSP) d_cnt[i] = 0;
}

// ---------------- forward DFT pass 1 (split-K tiled GEMM) ----------------
// grid (64 chunks, B), 256 threads. Block: X_partial[64 ch][32 cols] over 256 samples.
__global__ void k_fwd1(int src) {
    __shared__ float sh_h[64 * 65];
    __shared__ float sh_tw[64 * 32];
    const float* h = hbuf_c(src);
    int chunk = blockIdx.x, b = blockIdx.y, t = threadIdx.x;
    int s0 = chunk * 256;
    int c = t & 63;            // channel row
    int g = t >> 6;            // col group (8 cols each)
    float acc[8];
#pragma unroll
    for (int j = 0; j < 8; j++) acc[j] = 0.f;

    for (int piece = 0; piece < 4; piece++) {
        int sp0 = s0 + piece * 64;
        for (int idx = t; idx < 4096; idx += 256) {
            int cc = idx >> 6, ssl = idx & 63;
            sh_h[ssl * 65 + cc] = h[(b * HID + cc) * SS + sp0 + ssl];
        }
        for (int idx = t; idx < 2048; idx += 256) {
            int ssl = idx >> 5, col = idx & 31;
            float v = (col < 16) ? d_twc[(sp0 + ssl) * NM + col]
                                 : d_tws[(sp0 + ssl) * NM + (col - 16)];
            sh_tw[ssl * 32 + col] = v;
        }
        __syncthreads();
#pragma unroll 4
        for (int ssl = 0; ssl < 64; ssl++) {
            float xv = sh_h[ssl * 65 + c];
#pragma unroll
            for (int j = 0; j < 8; j++)
                acc[j] = fmaf(xv, sh_tw[ssl * 32 + g * 8 + j], acc[j]);
        }
        __syncthreads();
    }
#pragma unroll
    for (int j = 0; j < 8; j++)
        d_part[((b * 64 + chunk) * HID + c) * 32 + g * 8 + j] = acc[j];
}

// ---------------- forward DFT pass 2 (deterministic fp64 reduction) ----------------
__global__ void k_fwd2() {
    int i = blockIdx.x * 256 + threadIdx.x;        // B*HID*32 = 32768
    int b = i / (HID * 32);
    int rest = i - b * (HID * 32);
    const float* p = d_part + b * 64 * HID * 32 + rest;
    double acc = 0.0;
    for (int ch = 0; ch < 64; ch++) acc += (double)p[ch * HID * 32];
    d_Xf[i] = (float)acc;
}

// ---------------- spatial hash indices + histogram ----------------
__global__ void k_scidx(int src) {
    __shared__ float sC[260];
    __shared__ int hist[NPSP];
    const float* h = hbuf_c(src);
    int b = blockIdx.y, chunk = blockIdx.x, t = threadIdx.x;
    int s0 = chunk * 256;
    for (int i = t; i < NPSP; i += 256) hist[i] = 0;
    for (int i = t; i < 260; i += 256) {
        int s = s0 - 2 + i;
        s = max(0, min(SS - 1, s));
        const float* hp = h + (b * HID) * SS + s;
        float acc = 0.f;
#pragma unroll
        for (int c = 0; c < HID; c++) acc += hp[c * SS];
        sC[i] = acc;
    }
    __syncthreads();
    float w = sC[t] + sC[t + 1] + sC[t + 2] + sC[t + 3];
    int iv = (int)(w * 31.0f);                       // trunc toward zero
    int m = iv % NPSP; if (m < 0) m += NPSP;         // python-style mod
    d_idx[b * SS + s0 + t] = m;
    atomicAdd(&hist[m], 1);
    __syncthreads();
    for (int i = t; i < NPSP; i += 256)
        if (hist[i]) atomicAdd(&d_cnt[b * NPSP + i], hist[i]);
}

// ---------------- per-batch mix: mag/fr-idx, MHf, FRf, gate, combined spectrum ----------------
__global__ void k_mix(const float* __restrict__ fr_emb, const float* __restrict__ fr_W,
                      const float* __restrict__ fr_b,
                      const float* __restrict__ mhf_Wr, const float* __restrict__ mhf_Wi,
                      const float* __restrict__ gW1, const float* __restrict__ gb1,
                      const float* __restrict__ gW2, const float* __restrict__ gb2,
                      int layer) {
    __shared__ float shX[HID * 32];
    __shared__ float shMHre[HID * NM];
    __shared__ float shMHim[HID * NM];
    __shared__ float shFR[HID * NM];
    __shared__ float shg[192];
    __shared__ float shhid[64];
    __shared__ float shw[3];
    __shared__ int   shmi[16];
    __shared__ int   sh_ifr;
    int b = blockIdx.x, t = threadIdx.x;

    for (int i = t; i < HID * 32; i += 256) shX[i] = d_Xf[b * HID * 32 + i];
    __syncthreads();

    // spectral magnitude hash (fixed channel order, fp64)
    if (t < 16) {
        double acc = 0.0;
        for (int c = 0; c < HID; c++) {
            double re = (double)shX[c * 32 + t];
            double im = (double)shX[c * 32 + 16 + t];
            acc += sqrt(re * re + im * im);
        }
        float mag = (float)(acc / 64.0);
        shmi[t] = (int)(mag * 1000.0f);
    }
    // multi-head Fourier mix (independent of ifr)
    for (int u = t; u < 1024; u += 256) {            // u = h*256 + o*16 + k
        int h_ = u >> 8, o = (u >> 4) & 15, k = u & 15;
        float ar = 0.f, ai = 0.f;
        const float* Wr = mhf_Wr + (((layer * 4 + h_) * 16) * 16 + o) * 16 + k;  // i stride 256
        const float* Wi = mhf_Wi + (((layer * 4 + h_) * 16) * 16 + o) * 16 + k;
#pragma unroll
        for (int i = 0; i < 16; i++) {
            int cin = h_ * 16 + i;
            float re = shX[cin * 32 + k];
            float im = -shX[cin * 32 + 16 + k];
            float wr = Wr[i * 256];
            float wi = Wi[i * 256];
            ar = fmaf(re, wr, ar); ar = fmaf(-im, wi, ar);
            ai = fmaf(re, wi, ai); ai = fmaf(im, wr, ai);
        }
        int cout = h_ * 16 + o;
        shMHre[cout * 16 + k] = ar;
        shMHim[cout * 16 + k] = ai;
    }
    __syncthreads();
    if (t == 0) {
        int ssum = 0;
        for (int k = 0; k < 16; k++) ssum += shmi[k];
        int m = ssum % NPFR; if (m < 0) m += NPFR;
        sh_ifr = m;
    }
    __syncthreads();
    // spectral engram projection (real)
    {
        const float* e = fr_emb + (layer * NPFR + sh_ifr) * ED;
        for (int u = t; u < 1024; u += 256) {        // u = c*16+k
            const float* W = fr_W + layer * ED * 1024 + u;
            float acc = fr_b[layer * 1024 + u];
#pragma unroll
            for (int j = 0; j < ED; j++) acc = fmaf(e[j], W[j * 1024], acc);
            shFR[u] = acc;
        }
    }
    __syncthreads();
    // gate-input means
    if (t < 64) {
        double acc = 0.0;
        for (int p = 0; p < NPSP; p++)
            acc += (double)d_cnt[b * NPSP + p] * (double)d_P[p * HID + t];
        shg[t]       = (float)(acc / (double)SS);
        shg[64 + t]  = shMHre[t * 16 + 0] / (float)SS;
        shg[128 + t] = shFR[t * 16 + 0] / (float)SS;
    }
    __syncthreads();
    if (t < 64) {
        float acc = gb1[layer * 64 + t];
        const float* W1 = gW1 + layer * 192 * 64;
        for (int j = 0; j < 192; j++) acc = fmaf(shg[j], W1[j * 64 + t], acc);
        shhid[t] = fmaxf(acc, 0.f);
    }
    __syncthreads();
    if (t == 0) {
        float lg[3];
        const float* W2 = gW2 + layer * 64 * 3;
        for (int o = 0; o < 3; o++) {
            float acc = gb2[layer * 3 + o];
            for (int j = 0; j < 64; j++) acc = fmaf(shhid[j], W2[j * 3 + o], acc);
            lg[o] = acc;
        }
        float mx = fmaxf(lg[0], fmaxf(lg[1], lg[2]));
        float e0 = expf(lg[0] - mx), e1 = expf(lg[1] - mx), e2 = expf(lg[2] - mx);
        float inv = 1.f / (e0 + e1 + e2);
        shw[0] = e0 * inv; shw[1] = e1 * inv; shw[2] = e2 * inv;
        d_gw[b] = shw[0];
    }
    __syncthreads();
    // combined, irfft-prescaled spectrum
    float w2 = shw[1], w3 = shw[2];
    for (int u = t; u < 1024; u += 256) {            // u = c*16+k
        int k = u & 15;
        int c = u >> 4;
        float sc = ((k == 0) ? 1.f : 2.f) / (float)SS;
        d_Cf[(b * HID + c) * 32 + k]      = (w2 * shMHre[u] + w3 * shFR[u]) * sc;
        d_Cf[(b * HID + c) * 32 + 16 + k] = (w2 * shMHim[u]) * sc;
    }
}

// ---------------- combine: h_next = gelu( w1*P[idx] + inverse-DFT ) ----------------
__global__ void k_comb(int dst) {
    __shared__ float shC[HID * 32];
    float* hn = hbuf(dst);
    int b = blockIdx.y, chunk = blockIdx.x, t = threadIdx.x;
    for (int i = t; i < HID * 32; i += 256) shC[i] = d_Cf[b * HID * 32 + i];
    __syncthreads();
    int s = chunk * 256 + t;
    float tc[16], tsn[16];
#pragma unroll
    for (int k = 0; k < 16; k++) {
        tc[k]  = d_twc[s * NM + k];
        tsn[k] = d_tws[s * NM + k];
    }
    int idxv = d_idx[b * SS + s];
    const float* Prow = d_P + idxv * HID;
    float w1 = d_gw[b];
#pragma unroll 2
    for (int c = 0; c < HID; c++) {
        const float* C = shC + c * 32;
        float inv = 0.f;
#pragma unroll
        for (int k = 0; k < 16; k++) {
            inv = fmaf(C[k], tc[k], inv);
            inv = fmaf(-C[16 + k], tsn[k], inv);
        }
        float v = fmaf(w1, Prow[c], inv);
        float gl = 0.5f * v * (1.f + erff(v * 0.70710678118654752f));
        hn[(b * HID + c) * SS + s] = gl;
    }
}

// ---------------- proj: out = h @ proj_W + proj_b ----------------
__global__ void k_proj(int src, const float* __restrict__ W, const float* __restrict__ bias,
                       float* __restrict__ out) {
    const float* h = hbuf_c(src);
    int i = blockIdx.x * 256 + threadIdx.x;          // B*S
    int b = i >> 14;
    int s = i & (SS - 1);
    float acc = bias[0];
    const float* hp = h + b * HID * SS + s;
#pragma unroll
    for (int c = 0; c < HID; c++) acc = fmaf(hp[c * SS], __ldg(&W[c]), acc);
    out[i] = acc;
}

// ---------------- host ----------------
extern "C" void kernel_launch(void* const* d_in, const int* in_sizes, int n_in,
                              void* d_out, int out_size) {
    const float* x      = (const float*)d_in[0];
    const float* lift_W = (const float*)d_in[1];
    const float* lift_b = (const float*)d_in[2];
    const float* proj_W = (const float*)d_in[3];
    const float* proj_b = (const float*)d_in[4];
    const float* sp_emb = (const float*)d_in[5];
    const float* sp_W   = (const float*)d_in[6];
    const float* sp_b   = (const float*)d_in[7];
    const float* fr_emb = (const float*)d_in[8];
    const float* fr_W   = (const float*)d_in[9];
    const float* fr_b   = (const float*)d_in[10];
    const float* gW1    = (const float*)d_in[11];
    const float* gb1    = (const float*)d_in[12];
    const float* gW2    = (const float*)d_in[13];
    const float* gb2    = (const float*)d_in[14];
    const float* mhf_Wr = (const float*)d_in[15];
    const float* mhf_Wi = (const float*)d_in[16];
    float* out = (float*)d_out;

    k_init_tw<<<(SS * NM) / 256, 256>>>();
    k_lift<<<(BB * SS) / 256, 256>>>(x, lift_W, lift_b);

    int src = 0;
    for (int layer = 0; layer < NL; layer++) {
        int dst = src ^ 1;
        k_prep<<<125, 256>>>(sp_emb, sp_W, sp_b, layer);
        k_fwd1<<<dim3(64, BB), 256>>>(src);
        k_fwd2<<<(BB * HID * 32) / 256, 256>>>();
        k_scidx<<<dim3(64, BB), 256>>>(src);
        k_mix<<<BB, 256>>>(fr_emb, fr_W, fr_b, mhf_Wr, mhf_Wi, gW1, gb1, gW2, gb2, layer);
        k_comb<<<dim3(64, BB), 256>>>(dst);
        src = dst;
    }
    k_proj<<<(BB * SS) / 256, 256>>>(src, proj_W, proj_b, out);
}